// round 5
// baseline (speedup 1.0000x reference)
#include <cuda_runtime.h>
#include <cuda_bf16.h>
#include <math.h>

#define BS_   64
#define NQ_   300
#define T_    1280
#define ROWS_ (BS_ * NQ_)     // 19200
#define NBLK_ 592             // 4 * 148 SMs -> exactly one wave at 4 CTAs/SM
#define RPB_  33              // ceil-ish; blocks with row0+33>19200 take guarded path
#define THREADS_ 320

__device__ __forceinline__ float frcp(float x) {
    float r;
    asm("rcp.approx.f32 %0, %1;" : "=f"(r) : "f"(x));
    return r;
}

__global__ __launch_bounds__(THREADS_, 4)
void hungarian_cost_kernel(const float* __restrict__ logits,
                           const float* __restrict__ spans,
                           const float* __restrict__ tgt,
                           const float* __restrict__ refp,
                           float* __restrict__ out)
{
    __shared__ float4 s_row[RPB_];   // {cx, hw, rc1, pad}

    const int t    = threadIdx.x;
    const int row0 = blockIdx.x * RPB_;

    const float4 ta = __ldg(reinterpret_cast<const float4*>(tgt) + 2 * t);
    const float4 tb = __ldg(reinterpret_cast<const float4*>(tgt) + 2 * t + 1);

    float tcx[4], th[4];
    tcx[0] = ta.x; th[0] = 0.5f * ta.y;
    tcx[1] = ta.z; th[1] = 0.5f * ta.w;
    tcx[2] = tb.x; th[2] = 0.5f * tb.y;
    tcx[3] = tb.z; th[3] = 0.5f * tb.w;

    if (t < RPB_) {
        const int r = row0 + t;
        if (r < ROWS_) {
            const float l0 = __ldg(logits + 2 * r);
            const float l1 = __ldg(logits + 2 * r + 1);
            const float m  = fmaxf(l0, l1);
            const float e0 = __expf(l0 - m);
            const float e1 = __expf(l1 - m);
            const float p0 = __fdividef(e0, e0 + e1);

            const float cx = __ldg(spans + 2 * r);
            const float w  = __ldg(spans + 2 * r + 1);
            const float hw = 0.5f * w;
            const float x1 = cx - hw;
            const float x2 = cx + hw;

            const float r0 = __ldg(refp + 2 * r);
            const float r1 = __ldg(refp + 2 * r + 1);
            const float d0 = fabsf(x1 - r0);
            const float d1 = fabsf(x2 - r1);
            const float cref = sqrtf(fmaf(d0, d0, d1 * d1));

            s_row[t] = make_float4(cx, hw, cref - p0 + 1.0f, 0.0f);
        }
    }
    __syncthreads();

    float4* op = reinterpret_cast<float4*>(out + (size_t)row0 * T_) + t;

    if (row0 + RPB_ <= ROWS_) {          // uniform: fully-interior block
#pragma unroll 3
        for (int rr = 0; rr < RPB_; ++rr) {
            const float4 rd  = s_row[rr];
            const float cx   = rd.x;
            const float hw   = rd.y;
            const float rc1  = rd.z;

            float v[4];
#pragma unroll
            for (int i = 0; i < 4; ++i) {
                const float d0 = cx - tcx[i];
                const float e1 = hw - th[i];
                const float hs = hw + th[i];
                const float base = fmaf(2.0f, fabsf(e1), fabsf(d0)) + rc1;
                const float m     = fmaxf(fabsf(d0), fabsf(e1));
                const float ri    = hs - m;
                const float inter = fmaxf(ri, 0.0f);
                const float uni   = fmaf(2.0f, hs, -inter);
                const float enc   = fmaf(2.0f, hs, -ri);
                const float ru    = frcp(uni);
                const float re    = frcp(enc);
                const float acc = fmaf(-inter, ru, base);
                v[i] = fmaf(-uni, re, acc);
            }

            *op = make_float4(v[0], v[1], v[2], v[3]);
            op += T_ / 4;
        }
    } else {                              // tail blocks: per-row guard
#pragma unroll 3
        for (int rr = 0; rr < RPB_; ++rr) {
            if (row0 + rr < ROWS_) {
                const float4 rd  = s_row[rr];
                const float cx   = rd.x;
                const float hw   = rd.y;
                const float rc1  = rd.z;

                float v[4];
#pragma unroll
                for (int i = 0; i < 4; ++i) {
                    const float d0 = cx - tcx[i];
                    const float e1 = hw - th[i];
                    const float hs = hw + th[i];
                    const float base = fmaf(2.0f, fabsf(e1), fabsf(d0)) + rc1;
                    const float m     = fmaxf(fabsf(d0), fabsf(e1));
                    const float ri    = hs - m;
                    const float inter = fmaxf(ri, 0.0f);
                    const float uni   = fmaf(2.0f, hs, -inter);
                    const float enc   = fmaf(2.0f, hs, -ri);
                    const float ru    = frcp(uni);
                    const float re    = frcp(enc);
                    const float acc = fmaf(-inter, ru, base);
                    v[i] = fmaf(-uni, re, acc);
                }
                *op = make_float4(v[0], v[1], v[2], v[3]);
            }
            op += T_ / 4;
        }
    }
}

extern "C" void kernel_launch(void* const* d_in, const int* in_sizes, int n_in,
                              void* d_out, int out_size) {
    const float* logits = (const float*)d_in[0];
    const float* spans  = (const float*)d_in[1];
    const float* tgt    = (const float*)d_in[2];
    const float* refp   = (const float*)d_in[3];
    float* out = (float*)d_out;

    hungarian_cost_kernel<<<NBLK_, THREADS_>>>(logits, spans, tgt, refp, out);
}

// round 7
// speedup vs baseline: 1.2670x; 1.2670x over previous
#include <cuda_runtime.h>
#include <cuda_bf16.h>
#include <math.h>

#define BS_   64
#define NQ_   300
#define T_    1280            // 64 * 20 targets
#define ROWS_ (BS_ * NQ_)     // 19200
#define RPB_  16              // 1200 blocks, exact tiling
#define THREADS_ 320          // 1280 cols / 4 per thread

typedef unsigned long long u64;

__device__ __forceinline__ float frcp(float x) {
    float r;
    asm("rcp.approx.f32 %0, %1;" : "=f"(r) : "f"(x));
    return r;
}
__device__ __forceinline__ u64 pk(float lo, float hi) {
    u64 r;
    asm("mov.b64 %0, {%1, %2};" : "=l"(r) : "f"(lo), "f"(hi));
    return r;
}
__device__ __forceinline__ void upk(u64 v, float& lo, float& hi) {
    asm("mov.b64 {%0, %1}, %2;" : "=f"(lo), "=f"(hi) : "l"(v));
}
__device__ __forceinline__ u64 add2(u64 a, u64 b) {
    u64 r;
    asm("add.rn.f32x2 %0, %1, %2;" : "=l"(r) : "l"(a), "l"(b));
    return r;
}
__device__ __forceinline__ u64 mul2(u64 a, u64 b) {
    u64 r;
    asm("mul.rn.f32x2 %0, %1, %2;" : "=l"(r) : "l"(a), "l"(b));
    return r;
}
__device__ __forceinline__ u64 fma2(u64 a, u64 b, u64 c) {
    u64 r;
    asm("fma.rn.f32x2 %0, %1, %2, %3;" : "=l"(r) : "l"(a), "l"(b), "l"(c));
    return r;
}

__global__ __launch_bounds__(THREADS_, 4)
void hungarian_cost_kernel(const float* __restrict__ logits,   // [ROWS_, 2]
                           const float* __restrict__ spans,    // [ROWS_, 2] (cx, w)
                           const float* __restrict__ tgt,      // [T_, 2]    (cx, w)
                           const float* __restrict__ refp,     // [ROWS_, 2]
                           float* __restrict__ out)            // [ROWS_, T_]
{
    // per-row constants: {2*cx, w, rc1, pad}
    __shared__ float4 s_row[RPB_];

    const int t    = threadIdx.x;          // owns columns 4t..4t+3
    const int row0 = blockIdx.x * RPB_;

    // ---- per-thread target constants, packed (pair p covers cols 4t+2p, 4t+2p+1)
    const float4 ta = __ldg(reinterpret_cast<const float4*>(tgt) + 2 * t);
    const float4 tb = __ldg(reinterpret_cast<const float4*>(tgt) + 2 * t + 1);

    u64 NT2[2], NTW[2], TW[2];
    NT2[0] = pk(-2.0f * ta.x, -2.0f * ta.z);   // {-2*tcx}
    NT2[1] = pk(-2.0f * tb.x, -2.0f * tb.z);
    NTW[0] = pk(-ta.y, -ta.w);                 // {-tw}
    NTW[1] = pk(-tb.y, -tb.w);
    TW[0]  = pk(ta.y, ta.w);                   // {tw}
    TW[1]  = pk(tb.y, tb.w);
    const u64 NEG1 = pk(-1.0f, -1.0f);

    // ---- cooperative per-row constants (threads 0..RPB_-1) ----
    if (t < RPB_) {
        const int r = row0 + t;
        const float l0 = __ldg(logits + 2 * r);
        const float l1 = __ldg(logits + 2 * r + 1);
        const float m  = fmaxf(l0, l1);
        const float e0 = __expf(l0 - m);
        const float e1 = __expf(l1 - m);
        const float p0 = __fdividef(e0, e0 + e1);  // softmax prob class 0

        const float cx = __ldg(spans + 2 * r);
        const float w  = __ldg(spans + 2 * r + 1);
        const float hw = 0.5f * w;
        const float x1 = cx - hw;
        const float x2 = cx + hw;

        const float r0 = __ldg(refp + 2 * r);
        const float r1 = __ldg(refp + 2 * r + 1);
        const float d0 = fabsf(x1 - r0);
        const float d1 = fabsf(x2 - r1);
        const float cref = sqrtf(fmaf(d0, d0, d1 * d1));

        // rc1 = cost_reference - class_prob + 1  (+1 from -giou fold)
        s_row[t] = make_float4(2.0f * cx, w, cref - p0 + 1.0f, 0.0f);
    }
    __syncthreads();

    ulonglong2* op = reinterpret_cast<ulonglong2*>(out + (size_t)row0 * T_) + t;

#pragma unroll 4
    for (int rr = 0; rr < RPB_; ++rr) {
        const float4 rd = s_row[rr];
        const u64 c2p  = pk(rd.x, rd.x);   // {2cx, 2cx}
        const u64 wp   = pk(rd.y, rd.y);   // {w, w}
        const u64 rc1p = pk(rd.z, rd.z);   // {rc1, rc1}

        u64 vres[2];
#pragma unroll
        for (int p = 0; p < 2; ++p) {
            // packed diffs/sums. Doubled quantities: ri2 = s - M equals
            // 2*ri_true where s = w+tw, M = max(|2*dcx|, |dw|).
            const u64 dc2 = add2(c2p, NT2[p]);     // 2cx - 2tcx
            const u64 dw  = add2(wp,  NTW[p]);     // w - tw
            const u64 s   = add2(wp,  TW[p]);      // w + tw
            const u64 D   = add2(s, s);            // 2s  (doubled full sum)

            float dca, dcb, dwa, dwb;
            upk(dc2, dca, dcb);
            upk(dw,  dwa, dwb);

            const float Ma = fmaxf(fabsf(dca), fabsf(dwa));
            const float Mb = fmaxf(fabsf(dcb), fabsf(dwb));
            const u64 Mp  = pk(Ma, Mb);
            const u64 rip = fma2(Mp, NEG1, s);     // ri2 = s - M

            float ria, rib;
            upk(rip, ria, rib);
            const float ia = fmaxf(ria, 0.0f);
            const float ib = fmaxf(rib, 0.0f);
            const u64 ip = pk(ia, ib);             // I2 = max(ri2, 0)

            const u64 unip  = fma2(ip,  NEG1, D);  // U2 = 2s - I2
            const u64 uninp = fma2(D,   NEG1, ip); // -U2 = I2 - 2s
            const u64 encp  = fma2(rip, NEG1, D);  // E2 = 2s - ri2

            const u64 pp = mul2(uninp, encp);      // -(U2*E2)
            float pa, pb;
            upk(pp, pa, pb);
            const u64 rp = pk(frcp(pa), frcp(pb)); // -1/(U2*E2)

            const u64 numA = mul2(ip, encp);           // I2*E2
            const u64 numB = fma2(unip, unip, numA);   // + U2^2

            // L1 span: 0.5*|2dcx| + |dw|; then + rc1
            const float basea = fmaf(0.5f, fabsf(dca), fabsf(dwa));
            const float baseb = fmaf(0.5f, fabsf(dcb), fabsf(dwb));
            const u64 basefp = add2(pk(basea, baseb), rc1p);

            // v = basef - (I2*E2 + U2^2)/(U2*E2)  == base - inter/uni - uni/enc
            vres[p] = fma2(numB, rp, basefp);
        }

        ulonglong2 o;
        o.x = vres[0];
        o.y = vres[1];
        *op = o;
        op += T_ / 4;
    }
}

extern "C" void kernel_launch(void* const* d_in, const int* in_sizes, int n_in,
                              void* d_out, int out_size) {
    const float* logits = (const float*)d_in[0];  // pred_logits [64,300,2]
    const float* spans  = (const float*)d_in[1];  // pred_spans  [64,300,2]
    const float* tgt    = (const float*)d_in[2];  // tgt_spans   [1280,2]
    const float* refp   = (const float*)d_in[3];  // ref_points  [64,300,2]
    float* out = (float*)d_out;                   // [64,300,1280] fp32

    hungarian_cost_kernel<<<ROWS_ / RPB_, THREADS_>>>(logits, spans, tgt, refp, out);
}